// round 15
// baseline (speedup 1.0000x reference)
#include <cuda_runtime.h>
#include <cuda_fp16.h>
#include <cstdint>

#define NN 4096
#define DD 1024
#define BM 128
#define BN 128
#define KCH 32            // K per chunk (elems)
#define NCHUNK (DD / KCH)
#define NSTAGE 4
#define NTHREADS 512

typedef unsigned long long u64;

__device__ u64 g_ap[NN];
__device__ u64 g_an[NN];
__device__ int g_lab[NN];
__device__ int g_is64;
__device__ __half g_hi[NN * DD];   // 8 MB
__device__ __half g_lo[NN * DD];   // 8 MB

// ---------------------------------------------------------------------------
__global__ void detect_kernel(const int* __restrict__ lab32) {
    __shared__ int any;
    if (threadIdx.x == 0) any = 0;
    __syncthreads();
    int acc = 0;
    for (int i = 1 + 2 * threadIdx.x; i < 4096; i += 2 * blockDim.x)
        acc |= lab32[i];
    if (acc) atomicOr(&any, 1);
    __syncthreads();
    if (threadIdx.x == 0) g_is64 = (any == 0) ? 1 : 0;
}

__global__ void init_kernel(const int* __restrict__ lab32) {
    int i = blockIdx.x * blockDim.x + threadIdx.x;
    if (i < NN) {
        g_ap[i] = 0xFFFFFFFFFFFFFFFFull;
        g_an[i] = 0xFFFFFFFFFFFFFFFFull;
        g_lab[i] = g_is64 ? lab32[2 * i] : lab32[i];
    }
}

// fp32 -> (hi, lo) fp16 split, whole matrix, once.
__global__ void split_kernel(const float* __restrict__ X) {
    const int t = blockIdx.x * blockDim.x + threadIdx.x;   // 0 .. NN*DD/4-1
    float4 v = ((const float4*)X)[t];
    float f[4] = {v.x, v.y, v.z, v.w};
    __half h[4], l[4];
#pragma unroll
    for (int e = 0; e < 4; e++) {
        h[e] = __float2half_rn(f[e]);
        l[e] = __float2half_rn(f[e] - __half2float(h[e]));
    }
    ((uint2*)g_hi)[t] = *(uint2*)h;
    ((uint2*)g_lo)[t] = *(uint2*)l;
}

__device__ __forceinline__ unsigned float_order(float f) {
    unsigned u = __float_as_uint(f);
    return (u & 0x80000000u) ? ~u : (u | 0x80000000u);
}

__device__ __forceinline__ uint32_t smem_u32(const void* p) {
    uint32_t a;
    asm("{ .reg .u64 t; cvta.to.shared.u64 t, %1; cvt.u32.u64 %0, t; }"
        : "=r"(a) : "l"(p));
    return a;
}

#define LDSM4(r0, r1, r2, r3, addr) \
    asm volatile("ldmatrix.sync.aligned.m8n8.x4.shared.b16 {%0,%1,%2,%3}, [%4];" \
        : "=r"(r0), "=r"(r1), "=r"(r2), "=r"(r3) : "r"(addr))
#define LDSM2(r0, r1, addr) \
    asm volatile("ldmatrix.sync.aligned.m8n8.x2.shared.b16 {%0,%1}, [%2];" \
        : "=r"(r0), "=r"(r1) : "r"(addr))
#define MMA16816(d, a, b) \
    asm volatile("mma.sync.aligned.m16n8k16.row.col.f32.f16.f16.f32 " \
        "{%0,%1,%2,%3}, {%4,%5,%6,%7}, {%8,%9}, {%0,%1,%2,%3};" \
        : "+f"((d)[0]), "+f"((d)[1]), "+f"((d)[2]), "+f"((d)[3]) \
        : "r"((a)[0]), "r"((a)[1]), "r"((a)[2]), "r"((a)[3]), "r"((b)[0]), "r"((b)[1]))
// fp16-accumulate variant (Ootomo cross-term path)
#define MMA16816H(d, a, b) \
    asm volatile("mma.sync.aligned.m16n8k16.row.col.f16.f16.f16.f16 " \
        "{%0,%1}, {%2,%3,%4,%5}, {%6,%7}, {%0,%1};" \
        : "+r"((d)[0]), "+r"((d)[1]) \
        : "r"((a)[0]), "r"((a)[1]), "r"((a)[2]), "r"((a)[3]), "r"((b)[0]), "r"((b)[1]))
#define CP_ASYNC16(dst, src) \
    asm volatile("cp.async.cg.shared.global [%0], [%1], 16;" :: "r"(dst), "l"(src))
#define CP_COMMIT() asm volatile("cp.async.commit_group;" ::: "memory")
#define CP_WAIT2()  asm volatile("cp.async.wait_group 2;" ::: "memory")

// Tile smem layout: per 128-byte row: [hi: quads 0-3][lo: quads 4-7], quad =
// 16B = 8 fp16 (k-span 8). Physical quad = (logical ^ (row & 7)).
__device__ __forceinline__ uint32_t tile_addr(uint32_t base, int row, int q) {
    return base + row * 128 + ((q ^ (row & 7)) << 4);
}

#define TILE_BYTES (BM * 128)             // 16 KB  (hi+lo for one 128x32 tile)
#define STAGE_BYTES (2 * TILE_BYTES)      // A + B = 32 KB
#define SMEM_TOTAL (NSTAGE * STAGE_BYTES) // 128 KB

// ---------------------------------------------------------------------------
// 512 threads / 16 warps, warp tile 32x32.
// hh combo: fp32-accumulate MMA.  hl+lh combos: fp16-accumulate MMA chain,
// drained to the fp32 accumulators once per K-chunk (bounded rounding error).
// ---------------------------------------------------------------------------
__global__ __launch_bounds__(NTHREADS, 1)
void gemm_argmin_mma(const float* __restrict__ X) {
    extern __shared__ char smem[];
    const uint32_t sb = smem_u32(smem);

    __shared__ int labA[BM], labB[BN];
    __shared__ u64 rowAp[BM], rowAn[BM], colAp[BN], colAn[BN];

    const int t    = threadIdx.x;
    const int lane = t & 31;
    const int w    = t >> 5;

    // triangular decode: tile -> (bi, bj), bi >= bj
    const int tile = blockIdx.x;
    int bi = (int)((sqrtf(8.0f * (float)tile + 1.0f) - 1.0f) * 0.5f);
    while ((bi + 1) * (bi + 2) / 2 <= tile) bi++;
    while (bi * (bi + 1) / 2 > tile) bi--;
    const int bj = tile - bi * (bi + 1) / 2;
    const bool diag = (bi == bj);
    const int rowBase = bi * BM;
    const int colBase = bj * BN;

    if (t < BM) {
        labA[t] = g_lab[rowBase + t];
        labB[t] = g_lab[colBase + t];
        rowAp[t] = 0xFFFFFFFFFFFFFFFFull; rowAn[t] = 0xFFFFFFFFFFFFFFFFull;
        colAp[t] = 0xFFFFFFFFFFFFFFFFull; colAn[t] = 0xFFFFFFFFFFFFFFFFull;
    }

    // -------- async loader: 4 quads (16B) per thread per stage -------------
    auto issue_stage = [&](int c, int slot) {
        const uint32_t sbase = sb + slot * STAGE_BYTES;
#pragma unroll
        for (int i = 0; i < 4; i++) {
            const int id  = t + i * NTHREADS;
            const int tl  = id >> 10;
            const int row = (id >> 3) & 127;
            const int q   = id & 7;
            const int gr  = (tl ? colBase : rowBase) + row;
            const __half* src = (q < 4 ? g_hi : g_lo)
                                + (size_t)gr * DD + c * KCH + (q & 3) * 8;
            const uint32_t dst = tile_addr(sbase + tl * TILE_BYTES, row, q);
            CP_ASYNC16(dst, src);
        }
        CP_COMMIT();
    };

    float acc[2][4][4];
#pragma unroll
    for (int mt = 0; mt < 2; mt++)
#pragma unroll
        for (int nt = 0; nt < 4; nt++)
#pragma unroll
            for (int e = 0; e < 4; e++) acc[mt][nt][e] = 0.0f;

    const int wr = w >> 2;   // 0-3: rows wr*32..
    const int wc = w & 3;    // 0-3: cols wc*32..

    // prologue: stages 0..2
    issue_stage(0, 0);
    issue_stage(1, 1);
    issue_stage(2, 2);

    for (int c = 0; c < NCHUNK; c++) {
        CP_WAIT2();               // stage c landed
        __syncthreads();          // all warps done with slot (c-1)%4 reads
        if (c + 3 < NCHUNK) issue_stage(c + 3, (c + 3) & 3);
        else CP_COMMIT();         // keep group accounting uniform

        const uint32_t abase = sb + (c & 3) * STAGE_BYTES;
        const uint32_t bbase = abase + TILE_BYTES;

        // fp16 cross-term accumulators, zeroed each chunk
        uint32_t cacc[2][4][2];
#pragma unroll
        for (int mt = 0; mt < 2; mt++)
#pragma unroll
            for (int nt = 0; nt < 4; nt++) { cacc[mt][nt][0] = 0u; cacc[mt][nt][1] = 0u; }

#pragma unroll
        for (int ks = 0; ks < 2; ks++) {
            uint32_t ah[2][4], al[2][4], bh[4][2], bl[4][2];
            const int arow = wr * 32 + (lane & 7) + ((lane >> 3) & 1) * 8;
            const int akq  = ks * 2 + (lane >> 4);
#pragma unroll
            for (int mt = 0; mt < 2; mt++) {
                uint32_t ad = tile_addr(abase, arow + mt * 16, akq);
                LDSM4(ah[mt][0], ah[mt][1], ah[mt][2], ah[mt][3], ad);
                uint32_t ad2 = tile_addr(abase, arow + mt * 16, 4 + akq);
                LDSM4(al[mt][0], al[mt][1], al[mt][2], al[mt][3], ad2);
            }
            const int bl_  = lane & 15;
            const int brow = wc * 32 + (bl_ & 7);
            const int bkq  = ks * 2 + (bl_ >> 3);
#pragma unroll
            for (int nt = 0; nt < 4; nt++) {
                uint32_t bd = tile_addr(bbase, brow + nt * 8, bkq);
                LDSM2(bh[nt][0], bh[nt][1], bd);
                uint32_t bd2 = tile_addr(bbase, brow + nt * 8, 4 + bkq);
                LDSM2(bl[nt][0], bl[nt][1], bd2);
            }
            // hh: fp32 accumulate (dominant term)
#pragma unroll
            for (int mt = 0; mt < 2; mt++)
#pragma unroll
                for (int nt = 0; nt < 4; nt++)
                    MMA16816(acc[mt][nt], ah[mt], bh[nt]);
            // hl + lh: fp16 accumulate (small cross terms)
#pragma unroll
            for (int mt = 0; mt < 2; mt++)
#pragma unroll
                for (int nt = 0; nt < 4; nt++)
                    MMA16816H(cacc[mt][nt], ah[mt], bl[nt]);
#pragma unroll
            for (int mt = 0; mt < 2; mt++)
#pragma unroll
                for (int nt = 0; nt < 4; nt++)
                    MMA16816H(cacc[mt][nt], al[mt], bh[nt]);
        }

        // drain fp16 cross accumulators into fp32 (per chunk)
#pragma unroll
        for (int mt = 0; mt < 2; mt++)
#pragma unroll
            for (int nt = 0; nt < 4; nt++) {
                float2 p0 = __half22float2(*(__half2*)&cacc[mt][nt][0]);
                float2 p1 = __half22float2(*(__half2*)&cacc[mt][nt][1]);
                acc[mt][nt][0] += p0.x; acc[mt][nt][1] += p0.y;
                acc[mt][nt][2] += p1.x; acc[mt][nt][3] += p1.y;
            }
    }

    // ---- epilogue ---------------------------------------------------------
    const int rl = lane >> 2;
    const int cq = (lane & 3) * 2;

#pragma unroll
    for (int mt = 0; mt < 2; mt++)
#pragma unroll
        for (int rh = 0; rh < 2; rh++) {
            const int lr_ = wr * 32 + mt * 16 + rh * 8 + rl;
            const int r   = rowBase + lr_;
            const int lri = labA[lr_];
            u64 kap = 0xFFFFFFFFFFFFFFFFull, kan = 0xFFFFFFFFFFFFFFFFull;
#pragma unroll
            for (int nt = 0; nt < 4; nt++)
#pragma unroll
                for (int cp = 0; cp < 2; cp++) {
                    const int jc = wc * 32 + nt * 8 + cq + cp;
                    const int ccol = colBase + jc;
                    const bool same = (lri == labB[jc]);
                    const float v = acc[mt][nt][rh * 2 + cp];
                    const float vap = v + ((same && (r != ccol)) ? 0.0f : 2.0f);
                    const float van = v + (same ? 2.0f : 0.0f);
                    u64 k1 = ((u64)float_order(vap) << 32) | (unsigned)ccol;
                    u64 k2 = ((u64)float_order(van) << 32) | (unsigned)ccol;
                    kap = (k1 < kap) ? k1 : kap;
                    kan = (k2 < kan) ? k2 : kan;
                }
#pragma unroll
            for (int off = 1; off <= 2; off <<= 1) {
                u64 o1 = __shfl_xor_sync(0xffffffffu, kap, off);
                u64 o2 = __shfl_xor_sync(0xffffffffu, kan, off);
                kap = (o1 < kap) ? o1 : kap;
                kan = (o2 < kan) ? o2 : kan;
            }
            if ((lane & 3) == 0) {
                atomicMin(&rowAp[lr_], kap);
                atomicMin(&rowAn[lr_], kan);
            }
        }

    if (!diag) {
#pragma unroll
        for (int nt = 0; nt < 4; nt++)
#pragma unroll
            for (int cp = 0; cp < 2; cp++) {
                const int jc  = wc * 32 + nt * 8 + cq + cp;
                const int lcj = labB[jc];
                u64 kap = 0xFFFFFFFFFFFFFFFFull, kan = 0xFFFFFFFFFFFFFFFFull;
#pragma unroll
                for (int mt = 0; mt < 2; mt++)
#pragma unroll
                    for (int rh = 0; rh < 2; rh++) {
                        const int lr_ = wr * 32 + mt * 16 + rh * 8 + rl;
                        const int r = rowBase + lr_;
                        const bool same = (labA[lr_] == lcj);
                        const float v = acc[mt][nt][rh * 2 + cp];
                        const float vap = v + (same ? 0.0f : 2.0f);
                        const float van = v + (same ? 2.0f : 0.0f);
                        u64 k1 = ((u64)float_order(vap) << 32) | (unsigned)r;
                        u64 k2 = ((u64)float_order(van) << 32) | (unsigned)r;
                        kap = (k1 < kap) ? k1 : kap;
                        kan = (k2 < kan) ? k2 : kan;
                    }
#pragma unroll
                for (int off = 4; off <= 16; off <<= 1) {
                    u64 o1 = __shfl_xor_sync(0xffffffffu, kap, off);
                    u64 o2 = __shfl_xor_sync(0xffffffffu, kan, off);
                    kap = (o1 < kap) ? o1 : kap;
                    kan = (o2 < kan) ? o2 : kan;
                }
                if (rl == 0) {
                    atomicMin(&colAp[jc], kap);
                    atomicMin(&colAn[jc], kan);
                }
            }
    }
    __syncthreads();

    if (t < BM) {
        atomicMin(&g_ap[rowBase + t], rowAp[t]);
        atomicMin(&g_an[rowBase + t], rowAn[t]);
        if (!diag) {
            atomicMin(&g_ap[colBase + t], colAp[t]);
            atomicMin(&g_an[colBase + t], colAn[t]);
        }
    }
}

// ---------------------------------------------------------------------------
__global__ void gather_kernel(const float* __restrict__ X, float* __restrict__ out) {
    const int r     = blockIdx.x;
    const int which = blockIdx.y;
    const unsigned idx =
        (unsigned)((which ? g_an[r] : g_ap[r]) & 0xFFFFFFFFull);
    const float4* src = (const float4*)(X + (size_t)idx * DD);
    float4* dst = (float4*)(out + ((size_t)which * NN + r) * DD);
    for (int i = threadIdx.x; i < DD / 4; i += blockDim.x)
        dst[i] = src[i];
}

extern "C" void kernel_launch(void* const* d_in, const int* in_sizes, int n_in,
                              void* d_out, int out_size) {
    const float* X   = (const float*)d_in[0];
    const int*   lab = (const int*)d_in[1];
    float*       out = (float*)d_out;

    cudaFuncSetAttribute(gemm_argmin_mma,
                         cudaFuncAttributeMaxDynamicSharedMemorySize, SMEM_TOTAL);

    detect_kernel<<<1, 256>>>(lab);
    init_kernel<<<16, 256>>>(lab);
    split_kernel<<<(NN * DD / 4) / 256, 256>>>(X);
    const int ntiles = (NN / BM) * (NN / BM + 1) / 2;  // 528
    gemm_argmin_mma<<<ntiles, NTHREADS, SMEM_TOTAL>>>(X);
    gather_kernel<<<dim3(NN, 2), 256>>>(X, out);
}

// round 17
// speedup vs baseline: 1.1823x; 1.1823x over previous
#include <cuda_runtime.h>
#include <cuda_fp16.h>
#include <cstdint>

#define NN 4096
#define DD 1024
#define BM 128
#define BN 128
#define KCH 64            // K per chunk (elems) — 2 sub-tiles of 32
#define NCHUNK (DD / KCH) // 16
#define NSTAGE 3
#define NTHREADS 512

typedef unsigned long long u64;

__device__ u64 g_ap[NN];
__device__ u64 g_an[NN];
__device__ int g_lab[NN];
__device__ __half g_hi[NN * DD];   // 8 MB
__device__ __half g_lo[NN * DD];   // 8 MB

// ---------------------------------------------------------------------------
// init + in-block dtype detection (int64 vs int32 labels; JAX demotes without
// x64). Each block independently scans the odd 32-bit words of the first
// 4096 words: all-zero <=> int64 layout.
// ---------------------------------------------------------------------------
__global__ void init_kernel(const int* __restrict__ lab32) {
    __shared__ int any;
    if (threadIdx.x == 0) any = 0;
    __syncthreads();
    int acc = 0;
    for (int i = 1 + 2 * threadIdx.x; i < 4096; i += 2 * blockDim.x)
        acc |= lab32[i];
    if (acc) atomicOr(&any, 1);
    __syncthreads();
    const int is64 = (any == 0) ? 1 : 0;
    const int i = blockIdx.x * blockDim.x + threadIdx.x;
    if (i < NN) {
        g_ap[i] = 0xFFFFFFFFFFFFFFFFull;
        g_an[i] = 0xFFFFFFFFFFFFFFFFull;
        g_lab[i] = is64 ? lab32[2 * i] : lab32[i];
    }
}

// fp32 -> (hi, lo) fp16 split, whole matrix, once.
__global__ void split_kernel(const float* __restrict__ X) {
    const int t = blockIdx.x * blockDim.x + threadIdx.x;   // 0 .. NN*DD/4-1
    float4 v = ((const float4*)X)[t];
    float f[4] = {v.x, v.y, v.z, v.w};
    __half h[4], l[4];
#pragma unroll
    for (int e = 0; e < 4; e++) {
        h[e] = __float2half_rn(f[e]);
        l[e] = __float2half_rn(f[e] - __half2float(h[e]));
    }
    ((uint2*)g_hi)[t] = *(uint2*)h;
    ((uint2*)g_lo)[t] = *(uint2*)l;
}

__device__ __forceinline__ unsigned float_order(float f) {
    unsigned u = __float_as_uint(f);
    return (u & 0x80000000u) ? ~u : (u | 0x80000000u);
}

__device__ __forceinline__ uint32_t smem_u32(const void* p) {
    uint32_t a;
    asm("{ .reg .u64 t; cvta.to.shared.u64 t, %1; cvt.u32.u64 %0, t; }"
        : "=r"(a) : "l"(p));
    return a;
}

#define LDSM4(r0, r1, r2, r3, addr) \
    asm volatile("ldmatrix.sync.aligned.m8n8.x4.shared.b16 {%0,%1,%2,%3}, [%4];" \
        : "=r"(r0), "=r"(r1), "=r"(r2), "=r"(r3) : "r"(addr))
#define LDSM2(r0, r1, addr) \
    asm volatile("ldmatrix.sync.aligned.m8n8.x2.shared.b16 {%0,%1}, [%2];" \
        : "=r"(r0), "=r"(r1) : "r"(addr))
#define MMA16816(d, a, b) \
    asm volatile("mma.sync.aligned.m16n8k16.row.col.f32.f16.f16.f32 " \
        "{%0,%1,%2,%3}, {%4,%5,%6,%7}, {%8,%9}, {%0,%1,%2,%3};" \
        : "+f"((d)[0]), "+f"((d)[1]), "+f"((d)[2]), "+f"((d)[3]) \
        : "r"((a)[0]), "r"((a)[1]), "r"((a)[2]), "r"((a)[3]), "r"((b)[0]), "r"((b)[1]))
#define CP_ASYNC16(dst, src) \
    asm volatile("cp.async.cg.shared.global [%0], [%1], 16;" :: "r"(dst), "l"(src))
#define CP_COMMIT() asm volatile("cp.async.commit_group;" ::: "memory")
#define CP_WAIT1()  asm volatile("cp.async.wait_group 1;" ::: "memory")

// Sub-tile (128 rows x 32 k, hi+lo) smem layout: per 128-byte row:
// [hi: quads 0-3][lo: quads 4-7], quad = 16B = 8 fp16. phys quad = q ^ (row&7).
__device__ __forceinline__ uint32_t tile_addr(uint32_t base, int row, int q) {
    return base + row * 128 + ((q ^ (row & 7)) << 4);
}

#define SUB_BYTES   (BM * 128)            // 16 KB per 32-k sub-tile
#define TILE_BYTES  (2 * SUB_BYTES)       // 32 KB per K=64 tile (A or B)
#define STAGE_BYTES (2 * TILE_BYTES)      // A + B = 64 KB
#define SMEM_TOTAL  (NSTAGE * STAGE_BYTES) // 192 KB

// ---------------------------------------------------------------------------
// 512 threads / 16 warps, warp tile 32x32, K-chunk 64, 3-stage cp.async.
// ---------------------------------------------------------------------------
__global__ __launch_bounds__(NTHREADS, 1)
void gemm_argmin_mma(const float* __restrict__ X) {
    extern __shared__ char smem[];
    const uint32_t sb = smem_u32(smem);

    __shared__ int labA[BM], labB[BN];
    __shared__ u64 rowAp[BM], rowAn[BM], colAp[BN], colAn[BN];

    const int t    = threadIdx.x;
    const int lane = t & 31;
    const int w    = t >> 5;

    // triangular decode: tile -> (bi, bj), bi >= bj
    const int tile = blockIdx.x;
    int bi = (int)((sqrtf(8.0f * (float)tile + 1.0f) - 1.0f) * 0.5f);
    while ((bi + 1) * (bi + 2) / 2 <= tile) bi++;
    while (bi * (bi + 1) / 2 > tile) bi--;
    const int bj = tile - bi * (bi + 1) / 2;
    const bool diag = (bi == bj);
    const int rowBase = bi * BM;
    const int colBase = bj * BN;

    if (t < BM) {
        labA[t] = g_lab[rowBase + t];
        labB[t] = g_lab[colBase + t];
        rowAp[t] = 0xFFFFFFFFFFFFFFFFull; rowAn[t] = 0xFFFFFFFFFFFFFFFFull;
        colAp[t] = 0xFFFFFFFFFFFFFFFFull; colAn[t] = 0xFFFFFFFFFFFFFFFFull;
    }

    // -------- async loader: 8 x 16B per thread per stage (64 KB) -----------
    // id = t + i*512 in [0,4096): tl = id>>11 (0=A,1=B), sub = (id>>10)&1,
    // row = (id>>3)&127, q = id&7 (q<4: hi quad ; q>=4: lo quad)
    auto issue_stage = [&](int c, int slot) {
        const uint32_t sbase = sb + slot * STAGE_BYTES;
#pragma unroll
        for (int i = 0; i < 8; i++) {
            const int id  = t + i * NTHREADS;
            const int tl  = id >> 11;
            const int sub = (id >> 10) & 1;
            const int row = (id >> 3) & 127;
            const int q   = id & 7;
            const int gr  = (tl ? colBase : rowBase) + row;
            const __half* src = (q < 4 ? g_hi : g_lo)
                                + (size_t)gr * DD + c * KCH + sub * 32 + (q & 3) * 8;
            const uint32_t dst =
                tile_addr(sbase + tl * TILE_BYTES + sub * SUB_BYTES, row, q);
            CP_ASYNC16(dst, src);
        }
        CP_COMMIT();
    };

    float acc[2][4][4];
#pragma unroll
    for (int mt = 0; mt < 2; mt++)
#pragma unroll
        for (int nt = 0; nt < 4; nt++)
#pragma unroll
            for (int e = 0; e < 4; e++) acc[mt][nt][e] = 0.0f;

    const int wr = w >> 2;   // 0-3: rows wr*32..
    const int wc = w & 3;    // 0-3: cols wc*32..

    // prologue: stages 0,1
    issue_stage(0, 0);
    issue_stage(1, 1);

    int slot = 0;
    for (int c = 0; c < NCHUNK; c++) {
        CP_WAIT1();               // stage c landed (c+1 may pend)
        __syncthreads();          // all warps done reading slot (c-1)%3
        if (c + 2 < NCHUNK) {
            int ns = slot + 2; if (ns >= 3) ns -= 3;
            issue_stage(c + 2, ns);
        } else CP_COMMIT();       // keep group accounting uniform

        const uint32_t abase = sb + slot * STAGE_BYTES;
        const uint32_t bbase = abase + TILE_BYTES;

#pragma unroll
        for (int ks = 0; ks < 4; ks++) {
            const int sub = ks >> 1;
            const int ksk = ks & 1;
            const uint32_t asub = abase + sub * SUB_BYTES;
            const uint32_t bsub = bbase + sub * SUB_BYTES;
            uint32_t ah[2][4], al[2][4], bh[4][2], bl[4][2];
            const int arow = wr * 32 + (lane & 7) + ((lane >> 3) & 1) * 8;
            const int akq  = ksk * 2 + (lane >> 4);
#pragma unroll
            for (int mt = 0; mt < 2; mt++) {
                uint32_t ad = tile_addr(asub, arow + mt * 16, akq);
                LDSM4(ah[mt][0], ah[mt][1], ah[mt][2], ah[mt][3], ad);
                uint32_t ad2 = tile_addr(asub, arow + mt * 16, 4 + akq);
                LDSM4(al[mt][0], al[mt][1], al[mt][2], al[mt][3], ad2);
            }
            const int bl_  = lane & 15;
            const int brow = wc * 32 + (bl_ & 7);
            const int bkq  = ksk * 2 + (bl_ >> 3);
#pragma unroll
            for (int nt = 0; nt < 4; nt++) {
                uint32_t bd = tile_addr(bsub, brow + nt * 8, bkq);
                LDSM2(bh[nt][0], bh[nt][1], bd);
                uint32_t bd2 = tile_addr(bsub, brow + nt * 8, 4 + bkq);
                LDSM2(bl[nt][0], bl[nt][1], bd2);
            }
            // per-acc combo order stays hh, hl, lh (bit-identical values)
#pragma unroll
            for (int mt = 0; mt < 2; mt++)
#pragma unroll
                for (int nt = 0; nt < 4; nt++)
                    MMA16816(acc[mt][nt], ah[mt], bh[nt]);
#pragma unroll
            for (int mt = 0; mt < 2; mt++)
#pragma unroll
                for (int nt = 0; nt < 4; nt++)
                    MMA16816(acc[mt][nt], ah[mt], bl[nt]);
#pragma unroll
            for (int mt = 0; mt < 2; mt++)
#pragma unroll
                for (int nt = 0; nt < 4; nt++)
                    MMA16816(acc[mt][nt], al[mt], bh[nt]);
        }
        if (++slot >= 3) slot = 0;
    }

    // ---- epilogue (identical to R14) --------------------------------------
    const int rl = lane >> 2;
    const int cq = (lane & 3) * 2;

#pragma unroll
    for (int mt = 0; mt < 2; mt++)
#pragma unroll
        for (int rh = 0; rh < 2; rh++) {
            const int lr_ = wr * 32 + mt * 16 + rh * 8 + rl;
            const int r   = rowBase + lr_;
            const int lri = labA[lr_];
            u64 kap = 0xFFFFFFFFFFFFFFFFull, kan = 0xFFFFFFFFFFFFFFFFull;
#pragma unroll
            for (int nt = 0; nt < 4; nt++)
#pragma unroll
                for (int cp = 0; cp < 2; cp++) {
                    const int jc = wc * 32 + nt * 8 + cq + cp;
                    const int ccol = colBase + jc;
                    const bool same = (lri == labB[jc]);
                    const float v = acc[mt][nt][rh * 2 + cp];
                    const float vap = v + ((same && (r != ccol)) ? 0.0f : 2.0f);
                    const float van = v + (same ? 2.0f : 0.0f);
                    u64 k1 = ((u64)float_order(vap) << 32) | (unsigned)ccol;
                    u64 k2 = ((u64)float_order(van) << 32) | (unsigned)ccol;
                    kap = (k1 < kap) ? k1 : kap;
                    kan = (k2 < kan) ? k2 : kan;
                }
#pragma unroll
            for (int off = 1; off <= 2; off <<= 1) {
                u64 o1 = __shfl_xor_sync(0xffffffffu, kap, off);
                u64 o2 = __shfl_xor_sync(0xffffffffu, kan, off);
                kap = (o1 < kap) ? o1 : kap;
                kan = (o2 < kan) ? o2 : kan;
            }
            if ((lane & 3) == 0) {
                atomicMin(&rowAp[lr_], kap);
                atomicMin(&rowAn[lr_], kan);
            }
        }

    if (!diag) {
#pragma unroll
        for (int nt = 0; nt < 4; nt++)
#pragma unroll
            for (int cp = 0; cp < 2; cp++) {
                const int jc  = wc * 32 + nt * 8 + cq + cp;
                const int lcj = labB[jc];
                u64 kap = 0xFFFFFFFFFFFFFFFFull, kan = 0xFFFFFFFFFFFFFFFFull;
#pragma unroll
                for (int mt = 0; mt < 2; mt++)
#pragma unroll
                    for (int rh = 0; rh < 2; rh++) {
                        const int lr_ = wr * 32 + mt * 16 + rh * 8 + rl;
                        const int r = rowBase + lr_;
                        const bool same = (labA[lr_] == lcj);
                        const float v = acc[mt][nt][rh * 2 + cp];
                        const float vap = v + (same ? 0.0f : 2.0f);
                        const float van = v + (same ? 2.0f : 0.0f);
                        u64 k1 = ((u64)float_order(vap) << 32) | (unsigned)r;
                        u64 k2 = ((u64)float_order(van) << 32) | (unsigned)r;
                        kap = (k1 < kap) ? k1 : kap;
                        kan = (k2 < kan) ? k2 : kan;
                    }
#pragma unroll
                for (int off = 4; off <= 16; off <<= 1) {
                    u64 o1 = __shfl_xor_sync(0xffffffffu, kap, off);
                    u64 o2 = __shfl_xor_sync(0xffffffffu, kan, off);
                    kap = (o1 < kap) ? o1 : kap;
                    kan = (o2 < kan) ? o2 : kan;
                }
                if (rl == 0) {
                    atomicMin(&colAp[jc], kap);
                    atomicMin(&colAn[jc], kan);
                }
            }
    }
    __syncthreads();

    if (t < BM) {
        atomicMin(&g_ap[rowBase + t], rowAp[t]);
        atomicMin(&g_an[rowBase + t], rowAn[t]);
        if (!diag) {
            atomicMin(&g_ap[colBase + t], colAp[t]);
            atomicMin(&g_an[colBase + t], colAn[t]);
        }
    }
}

// ---------------------------------------------------------------------------
// Gather: one block per row r handles both outputs.
// out[0][r][:] = X[id_ap[r]], out[1][r][:] = X[id_an[r]]
// ---------------------------------------------------------------------------
__global__ void gather_kernel(const float* __restrict__ X, float* __restrict__ out) {
    const int r = blockIdx.x;
    const unsigned i0 = (unsigned)(g_ap[r] & 0xFFFFFFFFull);
    const unsigned i1 = (unsigned)(g_an[r] & 0xFFFFFFFFull);
    const float4* s0 = (const float4*)(X + (size_t)i0 * DD);
    const float4* s1 = (const float4*)(X + (size_t)i1 * DD);
    float4* d0 = (float4*)(out + (size_t)r * DD);
    float4* d1 = (float4*)(out + ((size_t)NN + r) * DD);
    for (int i = threadIdx.x; i < DD / 4; i += blockDim.x) {
        d0[i] = s0[i];
        d1[i] = s1[i];
    }
}

extern "C" void kernel_launch(void* const* d_in, const int* in_sizes, int n_in,
                              void* d_out, int out_size) {
    const float* X   = (const float*)d_in[0];
    const int*   lab = (const int*)d_in[1];
    float*       out = (float*)d_out;

    cudaFuncSetAttribute(gemm_argmin_mma,
                         cudaFuncAttributeMaxDynamicSharedMemorySize, SMEM_TOTAL);

    init_kernel<<<16, 256>>>(lab);
    split_kernel<<<(NN * DD / 4) / 256, 256>>>(X);
    const int ntiles = (NN / BM) * (NN / BM + 1) / 2;  // 528
    gemm_argmin_mma<<<ntiles, NTHREADS, SMEM_TOTAL>>>(X);
    gather_kernel<<<NN, 256>>>(X, out);
}